// round 2
// baseline (speedup 1.0000x reference)
#include <cuda_runtime.h>

// Problem constants
#define Bn   64
#define Dn   128
#define LCn  1024
#define LQn  128
#define TCn  128
#define NTn  8    // LCn / TCn
#define NEGV (-1e30f)

// Scratch (static device globals — no runtime allocation)
__device__ float g_S  [(size_t)Bn * LCn * LQn];        // 33.5 MB  S[b][c][q]
__device__ float g_Tp [(size_t)Bn * NTn * LQn * Dn];   // 33.5 MB  partial T per c-tile
__device__ float g_T  [(size_t)Bn * LQn * Dn];         // 4 MB     T[b][q][d]
__device__ float g_cp [Bn * NTn * LQn * 2];            // per-tile column (S2) LSE partials
__device__ float g_cs [Bn * LQn * 2];                  // combined column stats (m2, l2)

// ---------------------------------------------------------------------------
// K1: per (b, c-tile): S[c][q] = sum_d C[b,d,c]*w_m[d]*Q[b,d,q] + s_c[c] + s_q[q]
//     write S to global, and per-q (column) max/sumexp partials for S2.
// smem: Qs[128][128], Cs[128][128], sq[128], sc[128], w[384], cmadd[128]
// ---------------------------------------------------------------------------
__global__ __launch_bounds__(256) void k1_S(const float* __restrict__ C,
                                            const float* __restrict__ Q,
                                            const float* __restrict__ cmask,
                                            const float* __restrict__ w)
{
    extern __shared__ float sm[];
    float* Qs    = sm;            // [d][q] stride 128
    float* Cs    = sm + 16384;    // [d][c] stride 128 (later reused as Ss[c][q])
    float* sq    = sm + 32768;
    float* sc    = sm + 32896;
    float* wv    = sm + 33024;    // w_q | w_c | w_m
    float* cmadd = sm + 33408;

    const int b  = blockIdx.y;
    const int t  = blockIdx.x;
    const int c0 = t * TCn;
    const int tid = threadIdx.x;

    for (int i = tid; i < 384; i += 256) wv[i] = w[i];
    if (tid < 128) cmadd[tid] = (1.0f - cmask[b * LCn + c0 + tid]) * NEGV;

    // Load Q[b] (contiguous 128x128)
    {
        const float4* Qg = (const float4*)(Q + (size_t)b * Dn * LQn);
        float4* Qs4 = (float4*)Qs;
        #pragma unroll 4
        for (int i = tid; i < 4096; i += 256) Qs4[i] = Qg[i];
    }
    // Load C tile: Cs[d][c] = C[b, d, c0+c]
    {
        const float* Cg = C + (size_t)b * Dn * LCn + c0;
        #pragma unroll 4
        for (int i = tid; i < 4096; i += 256) {
            int d = i >> 5, x = i & 31;
            ((float4*)(Cs + d * 128))[x] = ((const float4*)(Cg + (size_t)d * LCn))[x];
        }
    }
    __syncthreads();

    // s_q[q] = sum_d Q[d][q]*w_q[d] ; s_c[c] = sum_d C[d][c]*w_c[d]
    if (tid < 128) {
        float s = 0.f;
        #pragma unroll 8
        for (int d = 0; d < 128; d++) s += Qs[d * 128 + tid] * wv[d];
        sq[tid] = s;
    } else {
        const int c = tid - 128;
        float s = 0.f;
        #pragma unroll 8
        for (int d = 0; d < 128; d++) s += Cs[d * 128 + c] * wv[128 + d];
        sc[c] = s;
    }
    __syncthreads();

    // Scale Cs rows by w_m[d]
    #pragma unroll 4
    for (int i = tid; i < 4096; i += 256) {
        int d = i >> 5;
        float m = wv[256 + d];
        float4 v = ((float4*)Cs)[i];
        v.x *= m; v.y *= m; v.z *= m; v.w *= m;
        ((float4*)Cs)[i] = v;
    }
    __syncthreads();

    // GEMM over d: acc[c][q], c = ty*8+i, q = tx*8+j
    const int tx = tid & 15, ty = tid >> 4;
    float acc[8][8];
    #pragma unroll
    for (int i = 0; i < 8; i++)
        #pragma unroll
        for (int j = 0; j < 8; j++) acc[i][j] = 0.f;

    const float* Cb = Cs + ty * 8;
    const float* Qb = Qs + tx * 8;
    for (int d = 0; d < 128; d++) {
        float4 a0 = *(const float4*)(Cb + d * 128);
        float4 a1 = *(const float4*)(Cb + d * 128 + 4);
        float4 q0 = *(const float4*)(Qb + d * 128);
        float4 q1 = *(const float4*)(Qb + d * 128 + 4);
        float av[8] = {a0.x, a0.y, a0.z, a0.w, a1.x, a1.y, a1.z, a1.w};
        float qv[8] = {q0.x, q0.y, q0.z, q0.w, q1.x, q1.y, q1.z, q1.w};
        #pragma unroll
        for (int i = 0; i < 8; i++)
            #pragma unroll
            for (int j = 0; j < 8; j++)
                acc[i][j] = fmaf(av[i], qv[j], acc[i][j]);
    }
    __syncthreads();   // GEMM reads done; safe to reuse Cs as Ss

    float* Ss = Cs;    // Ss[c][q] stride 128
    float sqr[8];
    #pragma unroll
    for (int j = 0; j < 8; j++) sqr[j] = sq[tx * 8 + j];

    float* gS = g_S + ((size_t)(b * LCn + c0)) * LQn;
    #pragma unroll
    for (int i = 0; i < 8; i++) {
        const int c = ty * 8 + i;
        const float scv = sc[c];
        float v[8];
        #pragma unroll
        for (int j = 0; j < 8; j++) v[j] = acc[i][j] + scv + sqr[j];
        float4 v0 = make_float4(v[0], v[1], v[2], v[3]);
        float4 v1 = make_float4(v[4], v[5], v[6], v[7]);
        *(float4*)(Ss + c * 128 + tx * 8)     = v0;
        *(float4*)(Ss + c * 128 + tx * 8 + 4) = v1;
        *(float4*)(gS + (size_t)c * LQn + tx * 8)     = v0;
        *(float4*)(gS + (size_t)c * LQn + tx * 8 + 4) = v1;
    }
    __syncthreads();

    // Column (S2 direction) partial stats: per q over this tile's 128 c rows
    if (tid < 128) {
        const int q = tid;
        float m = -3.4e38f;
        #pragma unroll 8
        for (int c = 0; c < 128; c++) m = fmaxf(m, Ss[c * 128 + q] + cmadd[c]);
        float l = 0.f;
        #pragma unroll 8
        for (int c = 0; c < 128; c++) l += __expf(Ss[c * 128 + q] + cmadd[c] - m);
        float* cp = g_cp + ((b * NTn + t) * LQn + q) * 2;
        cp[0] = m;
        cp[1] = l;
    }
}

// ---------------------------------------------------------------------------
// K2: combine per-tile column partials -> (m2, l2) per (b, q)
// ---------------------------------------------------------------------------
__global__ __launch_bounds__(128) void k2_colstats()
{
    const int b = blockIdx.x, q = threadIdx.x;
    float mt[NTn], lt[NTn];
    float m = -3.4e38f;
    #pragma unroll
    for (int t = 0; t < NTn; t++) {
        const float* cp = g_cp + ((b * NTn + t) * LQn + q) * 2;
        mt[t] = cp[0]; lt[t] = cp[1];
        m = fmaxf(m, mt[t]);
    }
    float l = 0.f;
    #pragma unroll
    for (int t = 0; t < NTn; t++) l += lt[t] * __expf(mt[t] - m);
    g_cs[(b * LQn + q) * 2]     = m;
    g_cs[(b * LQn + q) * 2 + 1] = l;
}

// ---------------------------------------------------------------------------
// K3: per (b, c-tile): Tp[q][d] = sum_c S2[c][q] * C[b,d,c]  (tile-partial)
// smem: Ss[128][128] (S tile -> S2), Cts[128][129] (C transposed), stats
// ---------------------------------------------------------------------------
__global__ __launch_bounds__(256) void k3_Tpart(const float* __restrict__ C,
                                                const float* __restrict__ cmask)
{
    extern __shared__ float sm[];
    float* Ss    = sm;            // [c][q] stride 128
    float* Cts   = sm + 16384;    // [c][d] stride 129 (conflict-free transpose)
    float* cmadd = sm + 32896;
    float* m2    = sm + 33024;
    float* il2   = sm + 33152;

    const int b = blockIdx.y, t = blockIdx.x, c0 = t * TCn;
    const int tid = threadIdx.x;

    {
        const float4* gS = (const float4*)(g_S + ((size_t)(b * LCn + c0)) * LQn);
        #pragma unroll 4
        for (int i = tid; i < 4096; i += 256) ((float4*)Ss)[i] = gS[i];
    }
    {
        const float* Cg = C + (size_t)b * Dn * LCn + c0;
        #pragma unroll 4
        for (int i = tid; i < 16384; i += 256) {
            int d = i >> 7, c = i & 127;
            Cts[c * 129 + d] = Cg[(size_t)d * LCn + c];
        }
    }
    if (tid < 128) {
        cmadd[tid] = (1.0f - cmask[b * LCn + c0 + tid]) * NEGV;
        m2[tid]  = g_cs[(b * LQn + tid) * 2];
        il2[tid] = 1.0f / g_cs[(b * LQn + tid) * 2 + 1];
    }
    __syncthreads();

    // Convert S -> S2 in place
    #pragma unroll 4
    for (int i = tid; i < 16384; i += 256) {
        int c = i >> 7, q = i & 127;
        Ss[i] = __expf(Ss[i] + cmadd[c] - m2[q]) * il2[q];
    }
    __syncthreads();

    // GEMM over c: Tp[q][d], q = ty*8+i, d = tx+16*j
    const int tx = tid & 15, ty = tid >> 4;
    float acc[8][8];
    #pragma unroll
    for (int i = 0; i < 8; i++)
        #pragma unroll
        for (int j = 0; j < 8; j++) acc[i][j] = 0.f;

    for (int c = 0; c < 128; c++) {
        float4 s0 = *(const float4*)(Ss + c * 128 + ty * 8);
        float4 s1 = *(const float4*)(Ss + c * 128 + ty * 8 + 4);
        float sv[8] = {s0.x, s0.y, s0.z, s0.w, s1.x, s1.y, s1.z, s1.w};
        float cv[8];
        #pragma unroll
        for (int j = 0; j < 8; j++) cv[j] = Cts[c * 129 + tx + 16 * j];
        #pragma unroll
        for (int i = 0; i < 8; i++)
            #pragma unroll
            for (int j = 0; j < 8; j++)
                acc[i][j] = fmaf(sv[i], cv[j], acc[i][j]);
    }

    float* tp = g_Tp + (size_t)(b * NTn + t) * LQn * Dn;
    #pragma unroll
    for (int i = 0; i < 8; i++)
        #pragma unroll
        for (int j = 0; j < 8; j++)
            tp[(ty * 8 + i) * Dn + tx + 16 * j] = acc[i][j];
}

// ---------------------------------------------------------------------------
// K3b: reduce 8 tile-partials -> T[b][q][d]   (deterministic, no atomics)
// ---------------------------------------------------------------------------
__global__ __launch_bounds__(256) void k3b_Treduce()
{
    const int idx = blockIdx.x * 256 + threadIdx.x;  // 0 .. B*LQ*D-1 (grid 4096x256)
    const int b = idx >> 14;          // / (LQn*Dn)
    const int r = idx & 16383;
    const size_t base = (size_t)b * NTn * 16384 + r;
    float s = 0.f;
    #pragma unroll
    for (int t = 0; t < NTn; t++) s += g_Tp[base + (size_t)t * 16384];
    g_T[idx] = s;
}

// ---------------------------------------------------------------------------
// K4: per (b, c-tile): row softmax -> S1; A = S1@Qt; Bt = S1@T;
//     write out[b, 0:128, c] = C, [128:256] = A, [256:384] = C*A, [384:512] = C*Bt
// smem: buf0 (Ss then Qt^T, 128*129), S1t[q][c] 128*129, Ts[q][d] 128*128, stats
// ---------------------------------------------------------------------------
__global__ __launch_bounds__(256) void k4_final(const float* __restrict__ C,
                                                const float* __restrict__ Q,
                                                const float* __restrict__ qmask,
                                                float* __restrict__ out)
{
    extern __shared__ float sm[];
    float* buf0  = sm;             // Ss[c][q] stride128, later Qts[q][d] stride129
    float* S1t   = sm + 16512;     // [q][c] stride 129
    float* Ts    = sm + 33024;     // [q][d] stride 128
    float* qmadd = sm + 49408;
    float* m1    = sm + 49536;
    float* il1   = sm + 49664;

    const int b = blockIdx.y, t = blockIdx.x, c0 = t * TCn;
    const int tid = threadIdx.x;

    float* Ss = buf0;
    {
        const float4* gS = (const float4*)(g_S + ((size_t)(b * LCn + c0)) * LQn);
        #pragma unroll 4
        for (int i = tid; i < 4096; i += 256) ((float4*)Ss)[i] = gS[i];
        const float4* gT = (const float4*)(g_T + (size_t)b * LQn * Dn);
        #pragma unroll 4
        for (int i = tid; i < 4096; i += 256) ((float4*)Ts)[i] = gT[i];
    }
    if (tid < 128) qmadd[tid] = (1.0f - qmask[b * LQn + tid]) * NEGV;
    __syncthreads();

    // Row (S1) stats: one warp per row group
    {
        const int warp = tid >> 5, lane = tid & 31;
        for (int c = warp; c < 128; c += 8) {
            float x0 = Ss[c * 128 + lane]      + qmadd[lane];
            float x1 = Ss[c * 128 + lane + 32] + qmadd[lane + 32];
            float x2 = Ss[c * 128 + lane + 64] + qmadd[lane + 64];
            float x3 = Ss[c * 128 + lane + 96] + qmadd[lane + 96];
            float m = fmaxf(fmaxf(x0, x1), fmaxf(x2, x3));
            #pragma unroll
            for (int off = 16; off; off >>= 1)
                m = fmaxf(m, __shfl_xor_sync(0xffffffffu, m, off));
            float l = __expf(x0 - m) + __expf(x1 - m) + __expf(x2 - m) + __expf(x3 - m);
            #pragma unroll
            for (int off = 16; off; off >>= 1)
                l += __shfl_xor_sync(0xffffffffu, l, off);
            if (lane == 0) { m1[c] = m; il1[c] = 1.0f / l; }
        }
    }
    __syncthreads();

    // S1 transposed: S1t[q][c]
    #pragma unroll 4
    for (int i = tid; i < 16384; i += 256) {
        int c = i >> 7, q = i & 127;
        S1t[q * 129 + c] = __expf(Ss[i] + qmadd[q] - m1[c]) * il1[c];
    }
    __syncthreads();

    // Overwrite buf0 with Q transposed: Qts[q][d] = Q[b,d,q]
    float* Qts = buf0;
    {
        const float* gQ = Q + (size_t)b * Dn * LQn;
        #pragma unroll 4
        for (int i = tid; i < 16384; i += 256) {
            int d = i >> 7, q = i & 127;
            Qts[q * 129 + d] = gQ[i];
        }
    }
    __syncthreads();

    const int tx = tid & 15, ty = tid >> 4;
    float* outB = out + (size_t)b * 4 * Dn * LCn;
    const float* Cb = C + (size_t)b * Dn * LCn;

    // ---- GEMM A: A[d][c] = sum_q Qts[q][d] * S1t[q][c];  d = ty*8+i, c = tx+16*j
    {
        float acc[8][8];
        #pragma unroll
        for (int i = 0; i < 8; i++)
            #pragma unroll
            for (int j = 0; j < 8; j++) acc[i][j] = 0.f;
        for (int q = 0; q < 128; q++) {
            float av[8], bv[8];
            #pragma unroll
            for (int i = 0; i < 8; i++) av[i] = Qts[q * 129 + ty * 8 + i];
            #pragma unroll
            for (int j = 0; j < 8; j++) bv[j] = S1t[q * 129 + tx + 16 * j];
            #pragma unroll
            for (int i = 0; i < 8; i++)
                #pragma unroll
                for (int j = 0; j < 8; j++)
                    acc[i][j] = fmaf(av[i], bv[j], acc[i][j]);
        }
        #pragma unroll
        for (int i = 0; i < 8; i++) {
            const int d = ty * 8 + i;
            const float* Crow = Cb + (size_t)d * LCn + c0;
            float* o1 = outB + (size_t)(Dn + d) * LCn + c0;
            float* o2 = outB + (size_t)(2 * Dn + d) * LCn + c0;
            #pragma unroll
            for (int j = 0; j < 8; j++) {
                const int c = tx + 16 * j;
                const float a = acc[i][j];
                o1[c] = a;
                o2[c] = Crow[c] * a;
            }
        }
    }

    // ---- GEMM Bt: Bt[d][c] = sum_q Ts[q][d] * S1t[q][c]
    {
        float acc[8][8];
        #pragma unroll
        for (int i = 0; i < 8; i++)
            #pragma unroll
            for (int j = 0; j < 8; j++) acc[i][j] = 0.f;
        for (int q = 0; q < 128; q++) {
            float av[8], bv[8];
            #pragma unroll
            for (int i = 0; i < 8; i++) av[i] = Ts[q * 128 + ty * 8 + i];
            #pragma unroll
            for (int j = 0; j < 8; j++) bv[j] = S1t[q * 129 + tx + 16 * j];
            #pragma unroll
            for (int i = 0; i < 8; i++)
                #pragma unroll
                for (int j = 0; j < 8; j++)
                    acc[i][j] = fmaf(av[i], bv[j], acc[i][j]);
        }
        #pragma unroll
        for (int i = 0; i < 8; i++) {
            const int d = ty * 8 + i;
            const float* Crow = Cb + (size_t)d * LCn + c0;
            float* o3 = outB + (size_t)(3 * Dn + d) * LCn + c0;
            #pragma unroll
            for (int j = 0; j < 8; j++) {
                const int c = tx + 16 * j;
                o3[c] = Crow[c] * acc[i][j];
            }
        }
    }

    // ---- Section 0: out[b, f, c0+..] = C[b, f, c0+..]
    #pragma unroll 4
    for (int i = tid; i < 4096; i += 256) {
        int f = i >> 5, x = i & 31;
        ((float4*)(outB + (size_t)f * LCn + c0))[x] =
            ((const float4*)(Cb + (size_t)f * LCn + c0))[x];
    }
}

// ---------------------------------------------------------------------------
extern "C" void kernel_launch(void* const* d_in, const int* in_sizes, int n_in,
                              void* d_out, int out_size)
{
    const float* C     = (const float*)d_in[0];
    const float* Q     = (const float*)d_in[1];
    const float* cmask = (const float*)d_in[2];
    const float* qmask = (const float*)d_in[3];
    const float* w     = (const float*)d_in[4];
    float* out = (float*)d_out;

    const int smem1 = 33536 * 4;   // 134,144 B
    const int smem3 = 33280 * 4;   // 133,120 B
    const int smem4 = 49792 * 4;   // 199,168 B
    cudaFuncSetAttribute(k1_S,     cudaFuncAttributeMaxDynamicSharedMemorySize, smem1);
    cudaFuncSetAttribute(k3_Tpart, cudaFuncAttributeMaxDynamicSharedMemorySize, smem3);
    cudaFuncSetAttribute(k4_final, cudaFuncAttributeMaxDynamicSharedMemorySize, smem4);

    dim3 grid(NTn, Bn);
    k1_S<<<grid, 256, smem1>>>(C, Q, cmask, w);
    k2_colstats<<<Bn, 128>>>();
    k3_Tpart<<<grid, 256, smem3>>>(C, cmask);
    k3b_Treduce<<<4096, 256>>>();
    k4_final<<<grid, 256, smem4>>>(C, Q, qmask, out);
}

// round 7
// speedup vs baseline: 1.2430x; 1.2430x over previous
#include <cuda_runtime.h>
#include <cuda_bf16.h>
#include <stdint.h>

#define Bn 64
#define Dn 128
#define LCn 1024
#define LQn 128
#define NTn 8
#define NEGV (-1e30f)

__device__ float g_S [(size_t)Bn * LCn * LQn];
__device__ float g_Tp[(size_t)Bn * 4 * LQn * Dn];
__device__ float g_T [(size_t)Bn * LQn * Dn];
__device__ float g_cp[Bn * NTn * LQn * 2];
__device__ float g_cs[Bn * LQn * 2];

// smem byte offsets: 4 operand tiles (128 rows x 128 k of bf16 = 32KB each),
// then a 128x132 fp32 bounce buffer, then small arrays.
#define A_HI 0
#define A_LO 32768
#define B_HI 65536
#define B_LO 98304
#define BOUNCE 131072
#define ST2 198656
#define SMEM_BYTES (ST2 + 5120)

__device__ __forceinline__ uint32_t s2u(const void* p) {
    uint32_t a;
    asm("{ .reg .u64 t; cvta.to.shared.u64 t, %1; cvt.u32.u64 %0, t; }" : "=r"(a) : "l"(p));
    return a;
}
// swizzled byte offset of element (row r, col k) in a 128x128 bf16 tile.
// 256B rows = 16 chunks of 16B. XOR only the low 3 bits of the chunk index
// with (r&7); preserve chunk bit 3 (the 128B-half selector).  <-- R6 bugfix
__device__ __forceinline__ uint32_t soff(int r, int k) {
    uint32_t c = (uint32_t)(k >> 3);
    uint32_t cs = (c & 8u) | ((c ^ (uint32_t)r) & 7u);
    return (uint32_t)(r << 8) + (cs << 4) + (uint32_t)((k & 7) << 1);
}
__device__ __forceinline__ uint2 split_pair(float v0, float v1) {
    __nv_bfloat16 h0 = __float2bfloat16(v0), h1 = __float2bfloat16(v1);
    __nv_bfloat16 l0 = __float2bfloat16(v0 - __bfloat162float(h0));
    __nv_bfloat16 l1 = __float2bfloat16(v1 - __bfloat162float(h1));
    __nv_bfloat162 H(h0, h1), L(l0, l1);
    uint2 r; r.x = *(uint32_t*)&H; r.y = *(uint32_t*)&L; return r;
}
__device__ __forceinline__ void ld4(uint32_t addr, uint32_t r[4]) {
    asm volatile("ldmatrix.sync.aligned.m8n8.x4.shared.b16 {%0,%1,%2,%3}, [%4];"
        : "=r"(r[0]), "=r"(r[1]), "=r"(r[2]), "=r"(r[3]) : "r"(addr));
}
__device__ __forceinline__ void mma16(float c[4], const uint32_t a[4],
                                      uint32_t b0, uint32_t b1) {
    asm volatile("mma.sync.aligned.m16n8k16.row.col.f32.bf16.bf16.f32 "
        "{%0,%1,%2,%3}, {%4,%5,%6,%7}, {%8,%9}, {%0,%1,%2,%3};"
        : "+f"(c[0]), "+f"(c[1]), "+f"(c[2]), "+f"(c[3])
        : "r"(a[0]), "r"(a[1]), "r"(a[2]), "r"(a[3]), "r"(b0), "r"(b1));
}
// 128x128x128 GEMM, bf16x3 fp32 emulation, accumulate into acc.
// Warp tile 32(M)x64(N); warp layout: m0=(wid&3)*32, n0=(wid>>2)*64.
__device__ __forceinline__ void gemm128(uint32_t sbase, int m0, int n0, int lane,
                                        float acc[2][8][4])
{
    const int arow = lane & 15, achk = (lane >> 4) << 3;
    const int brow = ((lane >> 4) << 3) | (lane & 7);
    const int bchk = ((lane >> 3) & 1) << 3;
    #pragma unroll
    for (int ks = 0; ks < 8; ks++) {
        uint32_t ah[2][4], al[2][4], bh[16], bl[16];
        #pragma unroll
        for (int mi = 0; mi < 2; mi++) {
            uint32_t o = soff(m0 + mi * 16 + arow, ks * 16 + achk);
            ld4(sbase + A_HI + o, ah[mi]);
            ld4(sbase + A_LO + o, al[mi]);
        }
        #pragma unroll
        for (int p = 0; p < 4; p++) {
            uint32_t o = soff(n0 + p * 16 + brow, ks * 16 + bchk);
            ld4(sbase + B_HI + o, &bh[p * 4]);
            ld4(sbase + B_LO + o, &bl[p * 4]);
        }
        #pragma unroll
        for (int mi = 0; mi < 2; mi++)
            #pragma unroll
            for (int ni = 0; ni < 8; ni++) {
                mma16(acc[mi][ni], ah[mi], bh[ni * 2], bh[ni * 2 + 1]);
                mma16(acc[mi][ni], ah[mi], bl[ni * 2], bl[ni * 2 + 1]);
                mma16(acc[mi][ni], al[mi], bh[ni * 2], bh[ni * 2 + 1]);
            }
    }
}
#define ZERO_ACC(acc) { \
    _Pragma("unroll") for (int _i = 0; _i < 2; _i++) \
    _Pragma("unroll") for (int _j = 0; _j < 8; _j++) \
    _Pragma("unroll") for (int _k = 0; _k < 4; _k++) (acc)[_i][_j][_k] = 0.f; }

// =====================================================================
// K1: S[c][q] = sum_d (C*w_m)[c][d] * Q[q][d] + s_c[c] + s_q[q]
// =====================================================================
__global__ __launch_bounds__(256) void k1_S(const float* __restrict__ C,
                                            const float* __restrict__ Q,
                                            const float* __restrict__ cmask,
                                            const float* __restrict__ w)
{
    extern __shared__ char sb[];
    const uint32_t sb32 = s2u(sb);
    float* bounce = (float*)(sb + BOUNCE);
    float* sc    = (float*)(sb + ST2);
    float* sq    = (float*)(sb + ST2 + 512);
    float* wv    = (float*)(sb + ST2 + 1024);
    float* cmadd = (float*)(sb + ST2 + 2560);
    float* scp   = (float*)(sb + ST2 + 3072);
    float* sqp   = (float*)(sb + ST2 + 4096);

    const int tid = threadIdx.x, wid = tid >> 5, lane = tid & 31;
    const int b = blockIdx.y, t = blockIdx.x, c0 = t * 128;

    for (int i = tid; i < 384; i += 256) wv[i] = w[i];
    if (tid < 128) cmadd[tid] = (1.0f - cmask[b * LCn + c0 + tid]) * NEGV;
    __syncthreads();

    // Stage A = (C*w_m)[c][d] hi/lo + s_c partials
    {
        const float* Cg = C + (size_t)b * Dn * LCn + c0;
        const int c = tid & 127;
        float av = 0.f;
        #pragma unroll 4
        for (int it = 0; it < 32; it++) {
            const int d2 = ((it * 256 + tid) >> 7) * 2;
            float v0 = Cg[(size_t)d2 * LCn + c];
            float v1 = Cg[(size_t)(d2 + 1) * LCn + c];
            av = fmaf(v0, wv[128 + d2], fmaf(v1, wv[129 + d2], av));
            uint2 p = split_pair(v0 * wv[256 + d2], v1 * wv[257 + d2]);
            uint32_t o = soff(c, d2);
            *(uint32_t*)(sb + A_HI + o) = p.x;
            *(uint32_t*)(sb + A_LO + o) = p.y;
        }
        scp[tid] = av;
    }
    // Stage B = Q[q][d] hi/lo + s_q partials
    {
        const float* Qg = Q + (size_t)b * Dn * LQn;
        const int q = tid & 127;
        float av = 0.f;
        #pragma unroll 4
        for (int it = 0; it < 32; it++) {
            const int d2 = ((it * 256 + tid) >> 7) * 2;
            float v0 = Qg[d2 * LQn + q];
            float v1 = Qg[(d2 + 1) * LQn + q];
            av = fmaf(v0, wv[d2], fmaf(v1, wv[d2 + 1], av));
            uint2 p = split_pair(v0, v1);
            uint32_t o = soff(q, d2);
            *(uint32_t*)(sb + B_HI + o) = p.x;
            *(uint32_t*)(sb + B_LO + o) = p.y;
        }
        sqp[tid] = av;
    }
    __syncthreads();
    if (tid < 128) sc[tid] = scp[tid] + scp[tid + 128];
    else { int q = tid & 127; sq[q] = sqp[q] + sqp[q + 128]; }
    __syncthreads();

    float acc[2][8][4];
    ZERO_ACC(acc);
    const int m0 = (wid & 3) * 32, n0 = (wid >> 2) * 64;
    gemm128(sb32, m0, n0, lane, acc);

    // D + sc + sq -> bounce[c][q] (stride 132)
    const int g = lane >> 2, l4 = lane & 3;
    #pragma unroll
    for (int mi = 0; mi < 2; mi++)
        #pragma unroll
        for (int ni = 0; ni < 8; ni++) {
            const int row = m0 + mi * 16 + g, col = n0 + ni * 8 + l4 * 2;
            float2 v;
            v.x = acc[mi][ni][0] + sc[row] + sq[col];
            v.y = acc[mi][ni][1] + sc[row] + sq[col + 1];
            *(float2*)&bounce[row * 132 + col] = v;
            v.x = acc[mi][ni][2] + sc[row + 8] + sq[col];
            v.y = acc[mi][ni][3] + sc[row + 8] + sq[col + 1];
            *(float2*)&bounce[(row + 8) * 132 + col] = v;
        }
    __syncthreads();

    float* gS = g_S + (size_t)(b * LCn + c0) * LQn;
    #pragma unroll 4
    for (int i = tid; i < 4096; i += 256) {
        int c = i >> 5, s = i & 31;
        *(float4*)(gS + c * LQn + s * 4) = *(float4*)(bounce + c * 132 + s * 4);
    }
    if (tid < 128) {
        const int q = tid;
        float m = -3.4e38f;
        #pragma unroll 8
        for (int c = 0; c < 128; c++) m = fmaxf(m, bounce[c * 132 + q] + cmadd[c]);
        float l = 0.f;
        #pragma unroll 8
        for (int c = 0; c < 128; c++) l += __expf(bounce[c * 132 + q] + cmadd[c] - m);
        float* cp = g_cp + ((b * NTn + t) * LQn + q) * 2;
        cp[0] = m; cp[1] = l;
    }
}

// =====================================================================
__global__ __launch_bounds__(128) void k2_colstats()
{
    const int b = blockIdx.x, q = threadIdx.x;
    float mt[NTn], lt[NTn], m = -3.4e38f;
    #pragma unroll
    for (int t = 0; t < NTn; t++) {
        const float* cp = g_cp + ((b * NTn + t) * LQn + q) * 2;
        mt[t] = cp[0]; lt[t] = cp[1]; m = fmaxf(m, mt[t]);
    }
    float l = 0.f;
    #pragma unroll
    for (int t = 0; t < NTn; t++) l += lt[t] * __expf(mt[t] - m);
    g_cs[(b * LQn + q) * 2] = m;
    g_cs[(b * LQn + q) * 2 + 1] = l;
}

// =====================================================================
// K3: partial T[q][d] = sum over 2 c-tiles of S2[q][c] * C[d][c]
// grid (4, Bn): block z handles tiles 2z, 2z+1; register accumulation.
// =====================================================================
__global__ __launch_bounds__(256) void k3_T(const float* __restrict__ C,
                                            const float* __restrict__ cmask)
{
    extern __shared__ char sb[];
    const uint32_t sb32 = s2u(sb);
    float* bounce = (float*)(sb + BOUNCE);
    float* m2    = (float*)(sb + ST2);
    float* il2   = (float*)(sb + ST2 + 512);
    float* cmadd = (float*)(sb + ST2 + 1024);

    const int tid = threadIdx.x, wid = tid >> 5, lane = tid & 31;
    const int b = blockIdx.y, z = blockIdx.x;

    if (tid < 128) {
        m2[tid]  = g_cs[(b * LQn + tid) * 2];
        il2[tid] = 1.0f / g_cs[(b * LQn + tid) * 2 + 1];
    }
    __syncthreads();
    const int q = tid & 127;
    const float mq = m2[q], ilq = il2[q];

    float acc[2][8][4];
    ZERO_ACC(acc);
    const int m0 = (wid & 3) * 32, n0 = (wid >> 2) * 64;

    for (int tt = 0; tt < 2; tt++) {
        const int t = z * 2 + tt;
        if (tid < 128) cmadd[tid] = (1.0f - cmask[b * LCn + t * 128 + tid]) * NEGV;
        __syncthreads();   // also guards smem reuse against prior gemm reads

        {   // A = S2[q][c] hi/lo
            const float* gS = g_S + (size_t)(b * LCn + t * 128) * LQn;
            #pragma unroll 2
            for (int it = 0; it < 32; it++) {
                const int c2 = ((it * 256 + tid) >> 7) * 2;
                float e0 = __expf(gS[c2 * LQn + q]       + cmadd[c2]     - mq) * ilq;
                float e1 = __expf(gS[(c2 + 1) * LQn + q] + cmadd[c2 + 1] - mq) * ilq;
                uint2 p = split_pair(e0, e1);
                uint32_t o = soff(q, c2);
                *(uint32_t*)(sb + A_HI + o) = p.x;
                *(uint32_t*)(sb + A_LO + o) = p.y;
            }
        }
        {   // B = C[d][c] hi/lo
            const float* Cg = C + (size_t)b * Dn * LCn + t * 128;
            const int c2 = (tid & 63) * 2;
            #pragma unroll 2
            for (int it = 0; it < 32; it++) {
                const int d = (it * 256 + tid) >> 6;
                float2 v = *(const float2*)(Cg + (size_t)d * LCn + c2);
                uint2 p = split_pair(v.x, v.y);
                uint32_t o = soff(d, c2);
                *(uint32_t*)(sb + B_HI + o) = p.x;
                *(uint32_t*)(sb + B_LO + o) = p.y;
            }
        }
        __syncthreads();
        gemm128(sb32, m0, n0, lane, acc);
    }

    // acc -> bounce[q][d]
    const int g = lane >> 2, l4 = lane & 3;
    #pragma unroll
    for (int mi = 0; mi < 2; mi++)
        #pragma unroll
        for (int ni = 0; ni < 8; ni++) {
            const int row = m0 + mi * 16 + g, col = n0 + ni * 8 + l4 * 2;
            *(float2*)&bounce[row * 132 + col] = make_float2(acc[mi][ni][0], acc[mi][ni][1]);
            *(float2*)&bounce[(row + 8) * 132 + col] = make_float2(acc[mi][ni][2], acc[mi][ni][3]);
        }
    __syncthreads();
    float* tp = g_Tp + (size_t)(b * 4 + z) * LQn * Dn;
    #pragma unroll 4
    for (int i = tid; i < 4096; i += 256) {
        int r = i >> 5, s = i & 31;
        *(float4*)(tp + r * Dn + s * 4) = *(float4*)(bounce + r * 132 + s * 4);
    }
}

// =====================================================================
__global__ __launch_bounds__(256) void k3r_Treduce()
{
    const int idx = blockIdx.x * 256 + threadIdx.x;
    const int b = idx >> 14, r = idx & 16383;
    const size_t base = (size_t)b * 4 * 16384 + r;
    g_T[idx] = (g_Tp[base] + g_Tp[base + 16384]) +
               (g_Tp[base + 2 * 16384] + g_Tp[base + 3 * 16384]);
}

// =====================================================================
// K4: S1 softmax; D1[c][d] = S1@Q^T; D2[c][d] = S1@T; fused 4-section out.
// =====================================================================
__global__ __launch_bounds__(256) void k4_final(const float* __restrict__ C,
                                                const float* __restrict__ Q,
                                                const float* __restrict__ qmask,
                                                float* __restrict__ out)
{
    extern __shared__ char sb[];
    const uint32_t sb32 = s2u(sb);
    float* bounce = (float*)(sb + BOUNCE);
    float* qmadd = (float*)(sb + ST2);
    float* m1    = (float*)(sb + ST2 + 512);
    float* il1   = (float*)(sb + ST2 + 1024);

    const int tid = threadIdx.x, wid = tid >> 5, lane = tid & 31;
    const int b = blockIdx.y, t = blockIdx.x, c0 = t * 128;

    if (tid < 128) qmadd[tid] = (1.0f - qmask[b * LQn + tid]) * NEGV;
    __syncthreads();

    const float* gS = g_S + (size_t)(b * LCn + c0) * LQn;

    // Row softmax stats
    for (int c = wid; c < 128; c += 8) {
        float x0 = gS[c * LQn + lane]      + qmadd[lane];
        float x1 = gS[c * LQn + lane + 32] + qmadd[lane + 32];
        float x2 = gS[c * LQn + lane + 64] + qmadd[lane + 64];
        float x3 = gS[c * LQn + lane + 96] + qmadd[lane + 96];
        float m = fmaxf(fmaxf(x0, x1), fmaxf(x2, x3));
        #pragma unroll
        for (int off = 16; off; off >>= 1) m = fmaxf(m, __shfl_xor_sync(~0u, m, off));
        float l = __expf(x0 - m) + __expf(x1 - m) + __expf(x2 - m) + __expf(x3 - m);
        #pragma unroll
        for (int off = 16; off; off >>= 1) l += __shfl_xor_sync(~0u, l, off);
        if (lane == 0) { m1[c] = m; il1[c] = 1.0f / l; }
    }
    __syncthreads();

    {   // A = S1[c][q] hi/lo
        const int q2 = (tid & 63) * 2;
        const float qa0 = qmadd[q2], qa1 = qmadd[q2 + 1];
        #pragma unroll 2
        for (int it = 0; it < 32; it++) {
            const int c = (it * 256 + tid) >> 6;
            float2 v = *(const float2*)(gS + c * LQn + q2);
            float m = m1[c], il = il1[c];
            uint2 p = split_pair(__expf(v.x + qa0 - m) * il, __expf(v.y + qa1 - m) * il);
            uint32_t o = soff(c, q2);
            *(uint32_t*)(sb + A_HI + o) = p.x;
            *(uint32_t*)(sb + A_LO + o) = p.y;
        }
    }
    {   // B1 = Q[d][q] hi/lo
        const float* Qg = Q + (size_t)b * Dn * LQn;
        const int q2 = (tid & 63) * 2;
        #pragma unroll 2
        for (int it = 0; it < 32; it++) {
            const int d = (it * 256 + tid) >> 6;
            float2 v = *(const float2*)(Qg + d * LQn + q2);
            uint2 p = split_pair(v.x, v.y);
            uint32_t o = soff(d, q2);
            *(uint32_t*)(sb + B_HI + o) = p.x;
            *(uint32_t*)(sb + B_LO + o) = p.y;
        }
    }
    __syncthreads();

    float acc[2][8][4];
    ZERO_ACC(acc);
    const int m0 = (wid & 3) * 32, n0 = (wid >> 2) * 64;
    gemm128(sb32, m0, n0, lane, acc);

    // D1 -> bounce transposed: bounce[d][c]
    const int g = lane >> 2, l4 = lane & 3;
    #pragma unroll
    for (int mi = 0; mi < 2; mi++)
        #pragma unroll
        for (int ni = 0; ni < 8; ni++) {
            const int row = m0 + mi * 16 + g, col = n0 + ni * 8 + l4 * 2;
            bounce[col * 132 + row]           = acc[mi][ni][0];
            bounce[(col + 1) * 132 + row]     = acc[mi][ni][1];
            bounce[col * 132 + row + 8]       = acc[mi][ni][2];
            bounce[(col + 1) * 132 + row + 8] = acc[mi][ni][3];
        }
    __syncthreads();

    float* outB = out + (size_t)b * 4 * Dn * LCn;
    const float* Cb = C + (size_t)b * Dn * LCn;

    // Epilogue 1: sections A and C*A; meanwhile stage B2 = T^T[d][q]
    #pragma unroll 2
    for (int i = tid; i < 4096; i += 256) {
        int d = i >> 5, c4 = (i & 31) * 4;
        float4 a = *(float4*)(bounce + d * 132 + c4);
        float4 cv = *(const float4*)(Cb + (size_t)d * LCn + c0 + c4);
        *(float4*)(outB + (size_t)(128 + d) * LCn + c0 + c4) = a;
        float4 ca = make_float4(cv.x * a.x, cv.y * a.y, cv.z * a.z, cv.w * a.w);
        *(float4*)(outB + (size_t)(256 + d) * LCn + c0 + c4) = ca;
    }
    {   // B2[d][q] = T[q][d] hi/lo (transposed staging)
        const float* gT = g_T + (size_t)b * LQn * Dn;
        const int d2 = (tid & 63) * 2;
        #pragma unroll 2
        for (int it = 0; it < 32; it++) {
            const int qq = (it * 256 + tid) >> 6;
            float2 v = *(const float2*)(gT + qq * Dn + d2);
            __nv_bfloat16 h0 = __float2bfloat16(v.x);
            __nv_bfloat16 l0 = __float2bfloat16(v.x - __bfloat162float(h0));
            __nv_bfloat16 h1 = __float2bfloat16(v.y);
            __nv_bfloat16 l1 = __float2bfloat16(v.y - __bfloat162float(h1));
            uint32_t o0 = soff(d2, qq), o1 = soff(d2 + 1, qq);
            *(__nv_bfloat16*)(sb + B_HI + o0) = h0;
            *(__nv_bfloat16*)(sb + B_LO + o0) = l0;
            *(__nv_bfloat16*)(sb + B_HI + o1) = h1;
            *(__nv_bfloat16*)(sb + B_LO + o1) = l1;
        }
    }
    __syncthreads();

    ZERO_ACC(acc);
    gemm128(sb32, m0, n0, lane, acc);

    #pragma unroll
    for (int mi = 0; mi < 2; mi++)
        #pragma unroll
        for (int ni = 0; ni < 8; ni++) {
            const int row = m0 + mi * 16 + g, col = n0 + ni * 8 + l4 * 2;
            bounce[col * 132 + row]           = acc[mi][ni][0];
            bounce[(col + 1) * 132 + row]     = acc[mi][ni][1];
            bounce[col * 132 + row + 8]       = acc[mi][ni][2];
            bounce[(col + 1) * 132 + row + 8] = acc[mi][ni][3];
        }
    __syncthreads();

    // Epilogue 2: section C*Bt + section 0 (C copy)
    #pragma unroll 2
    for (int i = tid; i < 4096; i += 256) {
        int d = i >> 5, c4 = (i & 31) * 4;
        float4 bt = *(float4*)(bounce + d * 132 + c4);
        float4 cv = *(const float4*)(Cb + (size_t)d * LCn + c0 + c4);
        *(float4*)(outB + (size_t)d * LCn + c0 + c4) = cv;
        float4 cb = make_float4(cv.x * bt.x, cv.y * bt.y, cv.z * bt.z, cv.w * bt.w);
        *(float4*)(outB + (size_t)(384 + d) * LCn + c0 + c4) = cb;
    }
}

// ---------------------------------------------------------------------------
extern "C" void kernel_launch(void* const* d_in, const int* in_sizes, int n_in,
                              void* d_out, int out_size)
{
    const float* C     = (const float*)d_in[0];
    const float* Q     = (const float*)d_in[1];
    const float* cmask = (const float*)d_in[2];
    const float* qmask = (const float*)d_in[3];
    const float* w     = (const float*)d_in[4];
    float* out = (float*)d_out;

    cudaFuncSetAttribute(k1_S,     cudaFuncAttributeMaxDynamicSharedMemorySize, SMEM_BYTES);
    cudaFuncSetAttribute(k3_T,     cudaFuncAttributeMaxDynamicSharedMemorySize, SMEM_BYTES);
    cudaFuncSetAttribute(k4_final, cudaFuncAttributeMaxDynamicSharedMemorySize, SMEM_BYTES);

    k1_S<<<dim3(NTn, Bn), 256, SMEM_BYTES>>>(C, Q, cmask, w);
    k2_colstats<<<Bn, 128>>>();
    k3_T<<<dim3(4, Bn), 256, SMEM_BYTES>>>(C, cmask);
    k3r_Treduce<<<4096, 256>>>();
    k4_final<<<dim3(NTn, Bn), 256, SMEM_BYTES>>>(C, Q, qmask, out);
}

// round 8
// speedup vs baseline: 1.3641x; 1.0974x over previous
#include <cuda_runtime.h>
#include <cuda_fp16.h>
#include <stdint.h>

#define Bn 64
#define Dn 128
#define LCn 1024
#define LQn 128
#define NTn 8
#define NEGV (-1e30f)

__device__ float g_S [(size_t)Bn * LCn * LQn];
__device__ float g_Tp[(size_t)Bn * 4 * LQn * Dn];
__device__ float g_T [(size_t)Bn * LQn * Dn];
__device__ float g_cp[Bn * NTn * LQn * 2];
__device__ float g_cs[Bn * LQn * 2];

// smem layout (K1/K3): A_HI | B_HI | B_LO | bounce | small
// (K4): A_HI | B1H | B1L | B2H | B2L ; bounces overlay operands post-GEMM
#define A_HI 0
#define B_HI 32768
#define B_LO 65536
#define BOUNCE 98304
#define B2H 98304
#define B2L 131072
#define BNC1 0
#define BNC2 69632
#define ST2 165888
#define SMEM_BYTES (ST2 + 5120)

__device__ __forceinline__ uint32_t s2u(const void* p) {
    uint32_t a;
    asm("{ .reg .u64 t; cvta.to.shared.u64 t, %1; cvt.u32.u64 %0, t; }" : "=r"(a) : "l"(p));
    return a;
}
// swizzled byte offset in a 128x128 half tile: 256B rows = 16 chunks of 16B;
// XOR low 3 chunk bits with (r&7), preserve chunk bit 3.
__device__ __forceinline__ uint32_t soff(int r, int k) {
    uint32_t c = (uint32_t)(k >> 3);
    uint32_t cs = (c & 8u) | ((c ^ (uint32_t)r) & 7u);
    return (uint32_t)(r << 8) + (cs << 4) + (uint32_t)((k & 7) << 1);
}
// pack two fp16 his
__device__ __forceinline__ uint32_t pack_hi(float v0, float v1) {
    __half2 h(__float2half_rn(v0), __float2half_rn(v1));
    return *(uint32_t*)&h;
}
// hi/lo split of a pair (lo on B side only)
__device__ __forceinline__ uint2 split_pair(float v0, float v1) {
    __half h0 = __float2half_rn(v0), h1 = __float2half_rn(v1);
    __half l0 = __float2half_rn(v0 - __half2float(h0));
    __half l1 = __float2half_rn(v1 - __half2float(h1));
    __half2 H(h0, h1), L(l0, l1);
    uint2 r; r.x = *(uint32_t*)&H; r.y = *(uint32_t*)&L; return r;
}
__device__ __forceinline__ void ld4(uint32_t addr, uint32_t r[4]) {
    asm volatile("ldmatrix.sync.aligned.m8n8.x4.shared.b16 {%0,%1,%2,%3}, [%4];"
        : "=r"(r[0]), "=r"(r[1]), "=r"(r[2]), "=r"(r[3]) : "r"(addr));
}
__device__ __forceinline__ void mma16(float c[4], const uint32_t a[4],
                                      uint32_t b0, uint32_t b1) {
    asm volatile("mma.sync.aligned.m16n8k16.row.col.f32.f16.f16.f32 "
        "{%0,%1,%2,%3}, {%4,%5,%6,%7}, {%8,%9}, {%0,%1,%2,%3};"
        : "+f"(c[0]), "+f"(c[1]), "+f"(c[2]), "+f"(c[3])
        : "r"(a[0]), "r"(a[1]), "r"(a[2]), "r"(a[3]), "r"(b0), "r"(b1));
}
// 128x128x128 GEMM, fp16 2-term (A hi-only, B hi+lo), accumulate into acc.
// Warp tile 32(M)x64(N); m0=(wid&3)*32, n0=(wid>>2)*64.
__device__ __forceinline__ void gemm2(uint32_t sbase, int m0, int n0, int lane,
                                      float acc[2][8][4])
{
    const int arow = lane & 15, achk = (lane >> 4) << 3;
    const int brow = ((lane >> 4) << 3) | (lane & 7);
    const int bchk = ((lane >> 3) & 1) << 3;
    #pragma unroll
    for (int ks = 0; ks < 8; ks++) {
        uint32_t ah[2][4], bh[16], bl[16];
        #pragma unroll
        for (int mi = 0; mi < 2; mi++)
            ld4(sbase + A_HI + soff(m0 + mi * 16 + arow, ks * 16 + achk), ah[mi]);
        #pragma unroll
        for (int p = 0; p < 4; p++) {
            uint32_t o = soff(n0 + p * 16 + brow, ks * 16 + bchk);
            ld4(sbase + B_HI + o, &bh[p * 4]);
            ld4(sbase + B_LO + o, &bl[p * 4]);
        }
        #pragma unroll
        for (int mi = 0; mi < 2; mi++)
            #pragma unroll
            for (int ni = 0; ni < 8; ni++) {
                mma16(acc[mi][ni], ah[mi], bh[ni * 2], bh[ni * 2 + 1]);
                mma16(acc[mi][ni], ah[mi], bl[ni * 2], bl[ni * 2 + 1]);
            }
    }
}
#define ZERO_ACC(acc) { \
    _Pragma("unroll") for (int _i = 0; _i < 2; _i++) \
    _Pragma("unroll") for (int _j = 0; _j < 8; _j++) \
    _Pragma("unroll") for (int _k = 0; _k < 4; _k++) (acc)[_i][_j][_k] = 0.f; }

// =====================================================================
// K1: S[c][q] = sum_d (C*w_m)[c][d] * Q[q][d] + s_c[c] + s_q[q]
// =====================================================================
__global__ __launch_bounds__(256) void k1_S(const float* __restrict__ C,
                                            const float* __restrict__ Q,
                                            const float* __restrict__ cmask,
                                            const float* __restrict__ w)
{
    extern __shared__ char sb[];
    const uint32_t sb32 = s2u(sb);
    float* bounce = (float*)(sb + BOUNCE);
    float* sc    = (float*)(sb + ST2);
    float* sq    = (float*)(sb + ST2 + 512);
    float* wv    = (float*)(sb + ST2 + 1024);
    float* cmadd = (float*)(sb + ST2 + 2560);
    float* scp   = (float*)(sb + ST2 + 3072);
    float* sqp   = (float*)(sb + ST2 + 4096);

    const int tid = threadIdx.x, wid = tid >> 5, lane = tid & 31;
    const int b = blockIdx.y, t = blockIdx.x, c0 = t * 128;

    for (int i = tid; i < 384; i += 256) wv[i] = w[i];
    if (tid < 128) cmadd[tid] = (1.0f - cmask[b * LCn + c0 + tid]) * NEGV;
    __syncthreads();

    // Stage A = (C*w_m)[c][d] hi + s_c partials
    {
        const float* Cg = C + (size_t)b * Dn * LCn + c0;
        const int c = tid & 127;
        float av = 0.f;
        #pragma unroll 4
        for (int it = 0; it < 32; it++) {
            const int d2 = ((it * 256 + tid) >> 7) * 2;
            float v0 = Cg[(size_t)d2 * LCn + c];
            float v1 = Cg[(size_t)(d2 + 1) * LCn + c];
            av = fmaf(v0, wv[128 + d2], fmaf(v1, wv[129 + d2], av));
            *(uint32_t*)(sb + A_HI + soff(c, d2)) =
                pack_hi(v0 * wv[256 + d2], v1 * wv[257 + d2]);
        }
        scp[tid] = av;
    }
    // Stage B = Q[q][d] hi/lo + s_q partials
    {
        const float* Qg = Q + (size_t)b * Dn * LQn;
        const int q = tid & 127;
        float av = 0.f;
        #pragma unroll 4
        for (int it = 0; it < 32; it++) {
            const int d2 = ((it * 256 + tid) >> 7) * 2;
            float v0 = Qg[d2 * LQn + q];
            float v1 = Qg[(d2 + 1) * LQn + q];
            av = fmaf(v0, wv[d2], fmaf(v1, wv[d2 + 1], av));
            uint2 p = split_pair(v0, v1);
            uint32_t o = soff(q, d2);
            *(uint32_t*)(sb + B_HI + o) = p.x;
            *(uint32_t*)(sb + B_LO + o) = p.y;
        }
        sqp[tid] = av;
    }
    __syncthreads();
    if (tid < 128) sc[tid] = scp[tid] + scp[tid + 128];
    else { int q = tid & 127; sq[q] = sqp[q] + sqp[q + 128]; }
    __syncthreads();

    float acc[2][8][4];
    ZERO_ACC(acc);
    const int m0 = (wid & 3) * 32, n0 = (wid >> 2) * 64;
    gemm2(sb32, m0, n0, lane, acc);

    // D + sc + sq -> bounce[c][q] (stride 132)
    const int g = lane >> 2, l4 = lane & 3;
    #pragma unroll
    for (int mi = 0; mi < 2; mi++)
        #pragma unroll
        for (int ni = 0; ni < 8; ni++) {
            const int row = m0 + mi * 16 + g, col = n0 + ni * 8 + l4 * 2;
            float2 v;
            v.x = acc[mi][ni][0] + sc[row] + sq[col];
            v.y = acc[mi][ni][1] + sc[row] + sq[col + 1];
            *(float2*)&bounce[row * 132 + col] = v;
            v.x = acc[mi][ni][2] + sc[row + 8] + sq[col];
            v.y = acc[mi][ni][3] + sc[row + 8] + sq[col + 1];
            *(float2*)&bounce[(row + 8) * 132 + col] = v;
        }
    __syncthreads();

    float* gS = g_S + (size_t)(b * LCn + c0) * LQn;
    #pragma unroll 4
    for (int i = tid; i < 4096; i += 256) {
        int c = i >> 5, s = i & 31;
        *(float4*)(gS + c * LQn + s * 4) = *(float4*)(bounce + c * 132 + s * 4);
    }
    if (tid < 128) {
        const int q = tid;
        float m = -3.4e38f;
        #pragma unroll 8
        for (int c = 0; c < 128; c++) m = fmaxf(m, bounce[c * 132 + q] + cmadd[c]);
        float l = 0.f;
        #pragma unroll 8
        for (int c = 0; c < 128; c++) l += __expf(bounce[c * 132 + q] + cmadd[c] - m);
        float* cp = g_cp + ((b * NTn + t) * LQn + q) * 2;
        cp[0] = m; cp[1] = l;
    }
}

// =====================================================================
__global__ __launch_bounds__(128) void k2_colstats()
{
    const int b = blockIdx.x, q = threadIdx.x;
    float mt[NTn], lt[NTn], m = -3.4e38f;
    #pragma unroll
    for (int t = 0; t < NTn; t++) {
        const float* cp = g_cp + ((b * NTn + t) * LQn + q) * 2;
        mt[t] = cp[0]; lt[t] = cp[1]; m = fmaxf(m, mt[t]);
    }
    float l = 0.f;
    #pragma unroll
    for (int t = 0; t < NTn; t++) l += lt[t] * __expf(mt[t] - m);
    g_cs[(b * LQn + q) * 2] = m;
    g_cs[(b * LQn + q) * 2 + 1] = l;
}

// =====================================================================
// K3: partial T[q][d] = sum over 2 c-tiles of S2[q][c] * C[d][c]
// =====================================================================
__global__ __launch_bounds__(256) void k3_T(const float* __restrict__ C,
                                            const float* __restrict__ cmask)
{
    extern __shared__ char sb[];
    const uint32_t sb32 = s2u(sb);
    float* bounce = (float*)(sb + BOUNCE);
    float* m2    = (float*)(sb + ST2);
    float* il2   = (float*)(sb + ST2 + 512);
    float* cmadd = (float*)(sb + ST2 + 1024);

    const int tid = threadIdx.x, wid = tid >> 5, lane = tid & 31;
    const int b = blockIdx.y, z = blockIdx.x;

    if (tid < 128) {
        m2[tid]  = g_cs[(b * LQn + tid) * 2];
        il2[tid] = 1.0f / g_cs[(b * LQn + tid) * 2 + 1];
    }
    __syncthreads();
    const int q = tid & 127;
    const float mq = m2[q], ilq = il2[q];

    float acc[2][8][4];
    ZERO_ACC(acc);
    const int m0 = (wid & 3) * 32, n0 = (wid >> 2) * 64;

    for (int tt = 0; tt < 2; tt++) {
        const int t = z * 2 + tt;
        if (tid < 128) cmadd[tid] = (1.0f - cmask[b * LCn + t * 128 + tid]) * NEGV;
        __syncthreads();

        {   // A = S2[q][c] hi
            const float* gS = g_S + (size_t)(b * LCn + t * 128) * LQn;
            #pragma unroll 2
            for (int it = 0; it < 32; it++) {
                const int c2 = ((it * 256 + tid) >> 7) * 2;
                float e0 = __expf(gS[c2 * LQn + q]       + cmadd[c2]     - mq) * ilq;
                float e1 = __expf(gS[(c2 + 1) * LQn + q] + cmadd[c2 + 1] - mq) * ilq;
                *(uint32_t*)(sb + A_HI + soff(q, c2)) = pack_hi(e0, e1);
            }
        }
        {   // B = C[d][c] hi/lo
            const float* Cg = C + (size_t)b * Dn * LCn + t * 128;
            const int c2 = (tid & 63) * 2;
            #pragma unroll 2
            for (int it = 0; it < 32; it++) {
                const int d = (it * 256 + tid) >> 6;
                float2 v = *(const float2*)(Cg + (size_t)d * LCn + c2);
                uint2 p = split_pair(v.x, v.y);
                uint32_t o = soff(d, c2);
                *(uint32_t*)(sb + B_HI + o) = p.x;
                *(uint32_t*)(sb + B_LO + o) = p.y;
            }
        }
        __syncthreads();
        gemm2(sb32, m0, n0, lane, acc);
    }

    const int g = lane >> 2, l4 = lane & 3;
    #pragma unroll
    for (int mi = 0; mi < 2; mi++)
        #pragma unroll
        for (int ni = 0; ni < 8; ni++) {
            const int row = m0 + mi * 16 + g, col = n0 + ni * 8 + l4 * 2;
            *(float2*)&bounce[row * 132 + col] = make_float2(acc[mi][ni][0], acc[mi][ni][1]);
            *(float2*)&bounce[(row + 8) * 132 + col] = make_float2(acc[mi][ni][2], acc[mi][ni][3]);
        }
    __syncthreads();
    float* tp = g_Tp + (size_t)(b * 4 + z) * LQn * Dn;
    #pragma unroll 4
    for (int i = tid; i < 4096; i += 256) {
        int r = i >> 5, s = i & 31;
        *(float4*)(tp + r * Dn + s * 4) = *(float4*)(bounce + r * 132 + s * 4);
    }
}

// =====================================================================
__global__ __launch_bounds__(256) void k3r_Treduce()
{
    const int idx = blockIdx.x * 256 + threadIdx.x;
    const int b = idx >> 14, r = idx & 16383;
    const size_t base = (size_t)b * 4 * 16384 + r;
    g_T[idx] = (g_Tp[base] + g_Tp[base + 16384]) +
               (g_Tp[base + 2 * 16384] + g_Tp[base + 3 * 16384]);
}

// =====================================================================
// K4: S1 softmax; merged dual GEMM D1[c][d]=S1@Q^T, D2[c][d]=S1@T;
//     single fused 4-section epilogue.
// =====================================================================
__global__ __launch_bounds__(256) void k4_final(const float* __restrict__ C,
                                                const float* __restrict__ Q,
                                                const float* __restrict__ qmask,
                                                float* __restrict__ out)
{
    extern __shared__ char sb[];
    const uint32_t sb32 = s2u(sb);
    float* qmadd = (float*)(sb + ST2);
    float* m1    = (float*)(sb + ST2 + 512);
    float* il1   = (float*)(sb + ST2 + 1024);

    const int tid = threadIdx.x, wid = tid >> 5, lane = tid & 31;
    const int b = blockIdx.y, t = blockIdx.x, c0 = t * 128;

    if (tid < 128) qmadd[tid] = (1.0f - qmask[b * LQn + tid]) * NEGV;
    __syncthreads();

    const float* gS = g_S + (size_t)(b * LCn + c0) * LQn;

    // Row softmax stats
    for (int c = wid; c < 128; c += 8) {
        float x0 = gS[c * LQn + lane]      + qmadd[lane];
        float x1 = gS[c * LQn + lane + 32] + qmadd[lane + 32];
        float x2 = gS[c * LQn + lane + 64] + qmadd[lane + 64];
        float x3 = gS[c * LQn + lane + 96] + qmadd[lane + 96];
        float m = fmaxf(fmaxf(x0, x1), fmaxf(x2, x3));
        #pragma unroll
        for (int off = 16; off; off >>= 1) m = fmaxf(m, __shfl_xor_sync(~0u, m, off));
        float l = __expf(x0 - m) + __expf(x1 - m) + __expf(x2 - m) + __expf(x3 - m);
        #pragma unroll
        for (int off = 16; off; off >>= 1) l += __shfl_xor_sync(~0u, l, off);
        if (lane == 0) { m1[c] = m; il1[c] = 1.0f / l; }
    }
    __syncthreads();

    {   // A = S1[c][q] hi
        const int q2 = (tid & 63) * 2;
        const float qa0 = qmadd[q2], qa1 = qmadd[q2 + 1];
        #pragma unroll 2
        for (int it = 0; it < 32; it++) {
            const int c = (it * 256 + tid) >> 6;
            float2 v = *(const float2*)(gS + c * LQn + q2);
            float m = m1[c], il = il1[c];
            *(uint32_t*)(sb + A_HI + soff(c, q2)) =
                pack_hi(__expf(v.x + qa0 - m) * il, __expf(v.y + qa1 - m) * il);
        }
    }
    {   // B1 = Q[d][q] hi/lo
        const float* Qg = Q + (size_t)b * Dn * LQn;
        const int q2 = (tid & 63) * 2;
        #pragma unroll 2
        for (int it = 0; it < 32; it++) {
            const int d = (it * 256 + tid) >> 6;
            float2 v = *(const float2*)(Qg + d * LQn + q2);
            uint2 p = split_pair(v.x, v.y);
            uint32_t o = soff(d, q2);
            *(uint32_t*)(sb + B_HI + o) = p.x;
            *(uint32_t*)(sb + B_LO + o) = p.y;
        }
    }
    {   // B2[d][q] = T[q][d] hi/lo (transposed staging)
        const float* gT = g_T + (size_t)b * LQn * Dn;
        const int d2 = (tid & 63) * 2;
        #pragma unroll 2
        for (int it = 0; it < 32; it++) {
            const int qq = (it * 256 + tid) >> 6;
            float2 v = *(const float2*)(gT + qq * Dn + d2);
            __half h0 = __float2half_rn(v.x);
            __half l0 = __float2half_rn(v.x - __half2float(h0));
            __half h1 = __float2half_rn(v.y);
            __half l1 = __float2half_rn(v.y - __half2float(h1));
            uint32_t o0 = soff(d2, qq), o1 = soff(d2 + 1, qq);
            *(__half*)(sb + B2H + o0) = h0;
            *(__half*)(sb + B2L + o0) = l0;
            *(__half*)(sb + B2H + o1) = h1;
            *(__half*)(sb + B2L + o1) = l1;
        }
    }
    __syncthreads();

    // Merged dual GEMM sharing A fragments
    float acc1[2][8][4], acc2[2][8][4];
    ZERO_ACC(acc1); ZERO_ACC(acc2);
    const int m0 = (wid & 3) * 32, n0 = (wid >> 2) * 64;
    {
        const int arow = lane & 15, achk = (lane >> 4) << 3;
        const int brow = ((lane >> 4) << 3) | (lane & 7);
        const int bchk = ((lane >> 3) & 1) << 3;
        #pragma unroll
        for (int ks = 0; ks < 8; ks++) {
            uint32_t ah[2][4];
            #pragma unroll
            for (int mi = 0; mi < 2; mi++)
                ld4(sb32 + A_HI + soff(m0 + mi * 16 + arow, ks * 16 + achk), ah[mi]);
            {
                uint32_t bh[16], bl[16];
                #pragma unroll
                for (int p = 0; p < 4; p++) {
                    uint32_t o = soff(n0 + p * 16 + brow, ks * 16 + bchk);
                    ld4(sb32 + B_HI + o, &bh[p * 4]);
                    ld4(sb32 + B_LO + o, &bl[p * 4]);
                }
                #pragma unroll
                for (int mi = 0; mi < 2; mi++)
                    #pragma unroll
                    for (int ni = 0; ni < 8; ni++) {
                        mma16(acc1[mi][ni], ah[mi], bh[ni * 2], bh[ni * 2 + 1]);
                        mma16(acc1[mi][ni], ah[mi], bl[ni * 2], bl[ni * 2 + 1]);
                    }
            }
            {
                uint32_t bh[16], bl[16];
                #pragma unroll
                for (int p = 0; p < 4; p++) {
                    uint32_t o = soff(n0 + p * 16 + brow, ks * 16 + bchk);
                    ld4(sb32 + B2H + o, &bh[p * 4]);
                    ld4(sb32 + B2L + o, &bl[p * 4]);
                }
                #pragma unroll
                for (int mi = 0; mi < 2; mi++)
                    #pragma unroll
                    for (int ni = 0; ni < 8; ni++) {
                        mma16(acc2[mi][ni], ah[mi], bh[ni * 2], bh[ni * 2 + 1]);
                        mma16(acc2[mi][ni], ah[mi], bl[ni * 2], bl[ni * 2 + 1]);
                    }
            }
        }
    }
    __syncthreads();   // operand tiles now dead; reuse as bounces

    float* bnc1 = (float*)(sb + BNC1);
    float* bnc2 = (float*)(sb + BNC2);
    const int g = lane >> 2, l4 = lane & 3;
    #pragma unroll
    for (int mi = 0; mi < 2; mi++)
        #pragma unroll
        for (int ni = 0; ni < 8; ni++) {
            const int row = m0 + mi * 16 + g, col = n0 + ni * 8 + l4 * 2;
            bnc1[col * 132 + row]           = acc1[mi][ni][0];
            bnc1[(col + 1) * 132 + row]     = acc1[mi][ni][1];
            bnc1[col * 132 + row + 8]       = acc1[mi][ni][2];
            bnc1[(col + 1) * 132 + row + 8] = acc1[mi][ni][3];
            bnc2[col * 132 + row]           = acc2[mi][ni][0];
            bnc2[(col + 1) * 132 + row]     = acc2[mi][ni][1];
            bnc2[col * 132 + row + 8]       = acc2[mi][ni][2];
            bnc2[(col + 1) * 132 + row + 8] = acc2[mi][ni][3];
        }
    __syncthreads();

    // Single fused epilogue: all 4 sections, one C read
    float* outB = out + (size_t)b * 4 * Dn * LCn;
    const float* Cb = C + (size_t)b * Dn * LCn;
    #pragma unroll 2
    for (int i = tid; i < 4096; i += 256) {
        int d = i >> 5, c4 = (i & 31) * 4;
        float4 a  = *(float4*)(bnc1 + d * 132 + c4);
        float4 bt = *(float4*)(bnc2 + d * 132 + c4);
        float4 cv = *(const float4*)(Cb + (size_t)d * LCn + c0 + c4);
        *(float4*)(outB + (size_t)d * LCn + c0 + c4) = cv;
        *(float4*)(outB + (size_t)(128 + d) * LCn + c0 + c4) = a;
        *(float4*)(outB + (size_t)(256 + d) * LCn + c0 + c4) =
            make_float4(cv.x * a.x, cv.y * a.y, cv.z * a.z, cv.w * a.w);
        *(float4*)(outB + (size_t)(384 + d) * LCn + c0 + c4) =
            make_float4(cv.x * bt.x, cv.y * bt.y, cv.z * bt.z, cv.w * bt.w);
    }
}

// ---------------------------------------------------------------------------
extern "C" void kernel_launch(void* const* d_in, const int* in_sizes, int n_in,
                              void* d_out, int out_size)
{
    const float* C     = (const float*)d_in[0];
    const float* Q     = (const float*)d_in[1];
    const float* cmask = (const float*)d_in[2];
    const float* qmask = (const float*)d_in[3];
    const float* w     = (const float*)d_in[4];
    float* out = (float*)d_out;

    cudaFuncSetAttribute(k1_S,     cudaFuncAttributeMaxDynamicSharedMemorySize, SMEM_BYTES);
    cudaFuncSetAttribute(k3_T,     cudaFuncAttributeMaxDynamicSharedMemorySize, SMEM_BYTES);
    cudaFuncSetAttribute(k4_final, cudaFuncAttributeMaxDynamicSharedMemorySize, SMEM_BYTES);

    k1_S<<<dim3(NTn, Bn), 256, SMEM_BYTES>>>(C, Q, cmask, w);
    k2_colstats<<<Bn, 128>>>();
    k3_T<<<dim3(4, Bn), 256, SMEM_BYTES>>>(C, cmask);
    k3r_Treduce<<<4096, 256>>>();
    k4_final<<<dim3(NTn, Bn), 256, SMEM_BYTES>>>(C, Q, qmask, out);
}

// round 12
// speedup vs baseline: 1.9208x; 1.4082x over previous
#include <cuda_runtime.h>
#include <cuda_fp16.h>
#include <stdint.h>

#define Bn 64
#define Dn 128
#define LCn 1024
#define LQn 128
#define NTn 8
#define NEGV (-1e30f)

__device__ float g_S [(size_t)Bn * LCn * LQn];
__device__ float g_Tp[(size_t)Bn * 4 * LQn * Dn];
__device__ float g_cp[Bn * NTn * LQn * 2];

// smem: operand tiles in [0, 96K); small arrays at 96K; fp32 bounce OVERLAYS
// the operand region after the GEMM (operands dead by then).
#define A_HI 0
#define B_HI 32768
#define B_LO 65536
// k4 layout: A 32K | B1H 16K | B1L 16K | B2H 16K | B2L 16K
#define B1H 32768
#define B1L 49152
#define B2H 65536
#define B2L 81920
#define SMALL 98304
#define SMEM1 (SMALL + 5120)
#define SMEM3 (SMALL + 1536)
#define SMEM4 (SMALL + 1536)

__device__ __forceinline__ uint32_t s2u(const void* p) {
    uint32_t a;
    asm("{ .reg .u64 t; cvta.to.shared.u64 t, %1; cvt.u32.u64 %0, t; }" : "=r"(a) : "l"(p));
    return a;
}
// swizzled byte offset in a (rows x 128) half tile: 256B rows = 16 chunks;
// XOR low 3 chunk bits with (r&7), preserve chunk bit 3.
__device__ __forceinline__ uint32_t soff(int r, int k) {
    uint32_t c = (uint32_t)(k >> 3);
    uint32_t cs = (c & 8u) | ((c ^ (uint32_t)r) & 7u);
    return (uint32_t)(r << 8) + (cs << 4) + (uint32_t)((k & 7) << 1);
}
__device__ __forceinline__ uint32_t pack_hi(float v0, float v1) {
    __half2 h(__float2half_rn(v0), __float2half_rn(v1));
    return *(uint32_t*)&h;
}
__device__ __forceinline__ uint2 split_pair(float v0, float v1) {
    __half h0 = __float2half_rn(v0), h1 = __float2half_rn(v1);
    __half l0 = __float2half_rn(v0 - __half2float(h0));
    __half l1 = __float2half_rn(v1 - __half2float(h1));
    __half2 H(h0, h1), L(l0, l1);
    uint2 r; r.x = *(uint32_t*)&H; r.y = *(uint32_t*)&L; return r;
}
__device__ __forceinline__ void ld4(uint32_t addr, uint32_t r[4]) {
    asm volatile("ldmatrix.sync.aligned.m8n8.x4.shared.b16 {%0,%1,%2,%3}, [%4];"
        : "=r"(r[0]), "=r"(r[1]), "=r"(r[2]), "=r"(r[3]) : "r"(addr));
}
__device__ __forceinline__ void mma16(float c[4], const uint32_t a[4],
                                      uint32_t b0, uint32_t b1) {
    asm volatile("mma.sync.aligned.m16n8k16.row.col.f32.f16.f16.f32 "
        "{%0,%1,%2,%3}, {%4,%5,%6,%7}, {%8,%9}, {%0,%1,%2,%3};"
        : "+f"(c[0]), "+f"(c[1]), "+f"(c[2]), "+f"(c[3])
        : "r"(a[0]), "r"(a[1]), "r"(a[2]), "r"(a[3]), "r"(b0), "r"(b1));
}
// 128x128x128 GEMM, fp16 2-term (A hi, B hi+lo). Warp tile 32x64.
__device__ __forceinline__ void gemm2(uint32_t sbase, int m0, int n0, int lane,
                                      float acc[2][8][4])
{
    const int arow = lane & 15, achk = (lane >> 4) << 3;
    const int brow = ((lane >> 4) << 3) | (lane & 7);
    const int bchk = ((lane >> 3) & 1) << 3;
    #pragma unroll
    for (int ks = 0; ks < 8; ks++) {
        uint32_t ah[2][4], bh[16], bl[16];
        #pragma unroll
        for (int mi = 0; mi < 2; mi++)
            ld4(sbase + A_HI + soff(m0 + mi * 16 + arow, ks * 16 + achk), ah[mi]);
        #pragma unroll
        for (int p = 0; p < 4; p++) {
            uint32_t o = soff(n0 + p * 16 + brow, ks * 16 + bchk);
            ld4(sbase + B_HI + o, &bh[p * 4]);
            ld4(sbase + B_LO + o, &bl[p * 4]);
        }
        #pragma unroll
        for (int mi = 0; mi < 2; mi++)
            #pragma unroll
            for (int ni = 0; ni < 8; ni++) {
                mma16(acc[mi][ni], ah[mi], bh[ni * 2], bh[ni * 2 + 1]);
                mma16(acc[mi][ni], ah[mi], bl[ni * 2], bl[ni * 2 + 1]);
            }
    }
}
#define ZERO8(acc) { \
    _Pragma("unroll") for (int _i = 0; _i < 2; _i++) \
    _Pragma("unroll") for (int _j = 0; _j < 8; _j++) \
    _Pragma("unroll") for (int _k = 0; _k < 4; _k++) (acc)[_i][_j][_k] = 0.f; }
#define ZERO4(acc) { \
    _Pragma("unroll") for (int _i = 0; _i < 2; _i++) \
    _Pragma("unroll") for (int _j = 0; _j < 4; _j++) \
    _Pragma("unroll") for (int _k = 0; _k < 4; _k++) (acc)[_i][_j][_k] = 0.f; }

// =====================================================================
// K1: S[c][q] = sum_d (C*w_m)[c][d]*Q[q][d] + s_c + s_q; column LSE partials
// =====================================================================
__global__ __launch_bounds__(256, 2) void k1_S(const float* __restrict__ C,
                                               const float* __restrict__ Q,
                                               const float* __restrict__ cmask,
                                               const float* __restrict__ w)
{
    extern __shared__ char sb[];
    const uint32_t sb32 = s2u(sb);
    float* bounce = (float*)sb;              // overlays operands post-GEMM
    float* sc    = (float*)(sb + SMALL);
    float* sq    = (float*)(sb + SMALL + 512);
    float* wv    = (float*)(sb + SMALL + 1024);
    float* cmadd = (float*)(sb + SMALL + 2560);
    float* scp   = (float*)(sb + SMALL + 3072);
    float* sqp   = (float*)(sb + SMALL + 4096);

    const int tid = threadIdx.x, wid = tid >> 5, lane = tid & 31;
    const int b = blockIdx.y, t = blockIdx.x, c0 = t * 128;

    for (int i = tid; i < 384; i += 256) wv[i] = w[i];
    if (tid < 128) cmadd[tid] = (1.0f - cmask[b * LCn + c0 + tid]) * NEGV;
    __syncthreads();

    {   // A = (C*w_m)[c][d] hi + s_c partials
        const float* Cg = C + (size_t)b * Dn * LCn + c0;
        const int c = tid & 127;
        float av = 0.f;
        #pragma unroll 4
        for (int it = 0; it < 32; it++) {
            const int d2 = ((it * 256 + tid) >> 7) * 2;
            float v0 = Cg[(size_t)d2 * LCn + c];
            float v1 = Cg[(size_t)(d2 + 1) * LCn + c];
            av = fmaf(v0, wv[128 + d2], fmaf(v1, wv[129 + d2], av));
            *(uint32_t*)(sb + A_HI + soff(c, d2)) =
                pack_hi(v0 * wv[256 + d2], v1 * wv[257 + d2]);
        }
        scp[tid] = av;
    }
    {   // B = Q[q][d] hi/lo + s_q partials
        const float* Qg = Q + (size_t)b * Dn * LQn;
        const int q = tid & 127;
        float av = 0.f;
        #pragma unroll 4
        for (int it = 0; it < 32; it++) {
            const int d2 = ((it * 256 + tid) >> 7) * 2;
            float v0 = Qg[d2 * LQn + q];
            float v1 = Qg[(d2 + 1) * LQn + q];
            av = fmaf(v0, wv[d2], fmaf(v1, wv[d2 + 1], av));
            uint2 p = split_pair(v0, v1);
            uint32_t o = soff(q, d2);
            *(uint32_t*)(sb + B_HI + o) = p.x;
            *(uint32_t*)(sb + B_LO + o) = p.y;
        }
        sqp[tid] = av;
    }
    __syncthreads();
    if (tid < 128) sc[tid] = scp[tid] + scp[tid + 128];
    else { int q = tid & 127; sq[q] = sqp[q] + sqp[q + 128]; }
    __syncthreads();

    float acc[2][8][4];
    ZERO8(acc);
    const int m0 = (wid & 3) * 32, n0 = (wid >> 2) * 64;
    gemm2(sb32, m0, n0, lane, acc);
    __syncthreads();   // operands dead; bounce overlays them

    const int g = lane >> 2, l4 = lane & 3;
    #pragma unroll
    for (int mi = 0; mi < 2; mi++)
        #pragma unroll
        for (int ni = 0; ni < 8; ni++) {
            const int row = m0 + mi * 16 + g, col = n0 + ni * 8 + l4 * 2;
            float2 v;
            v.x = acc[mi][ni][0] + sc[row] + sq[col];
            v.y = acc[mi][ni][1] + sc[row] + sq[col + 1];
            *(float2*)&bounce[row * 132 + col] = v;
            v.x = acc[mi][ni][2] + sc[row + 8] + sq[col];
            v.y = acc[mi][ni][3] + sc[row + 8] + sq[col + 1];
            *(float2*)&bounce[(row + 8) * 132 + col] = v;
        }
    __syncthreads();

    float* gS = g_S + (size_t)(b * LCn + c0) * LQn;
    #pragma unroll 4
    for (int i = tid; i < 4096; i += 256) {
        int c = i >> 5, s = i & 31;
        *(float4*)(gS + c * LQn + s * 4) = *(float4*)(bounce + c * 132 + s * 4);
    }
    if (tid < 128) {
        const int q = tid;
        float m = -3.4e38f;
        #pragma unroll 8
        for (int c = 0; c < 128; c++) m = fmaxf(m, bounce[c * 132 + q] + cmadd[c]);
        float l = 0.f;
        #pragma unroll 8
        for (int c = 0; c < 128; c++) l += __expf(bounce[c * 132 + q] + cmadd[c] - m);
        float* cp = g_cp + ((b * NTn + t) * LQn + q) * 2;
        cp[0] = m; cp[1] = l;
    }
}

// =====================================================================
// K3: partial T[q][d] over 2 c-tiles; column stats combined inline.
// =====================================================================
__global__ __launch_bounds__(256, 2) void k3_T(const float* __restrict__ C,
                                               const float* __restrict__ cmask)
{
    extern __shared__ char sb[];
    const uint32_t sb32 = s2u(sb);
    float* bounce = (float*)sb;
    float* m2    = (float*)(sb + SMALL);
    float* il2   = (float*)(sb + SMALL + 512);
    float* cmadd = (float*)(sb + SMALL + 1024);

    const int tid = threadIdx.x, wid = tid >> 5, lane = tid & 31;
    const int b = blockIdx.y, z = blockIdx.x;

    if (tid < 128) {   // inline colstat combine (was k2)
        float mt[NTn], lt[NTn], m = -3.4e38f;
        #pragma unroll
        for (int t = 0; t < NTn; t++) {
            const float* cp = g_cp + ((b * NTn + t) * LQn + tid) * 2;
            mt[t] = cp[0]; lt[t] = cp[1]; m = fmaxf(m, mt[t]);
        }
        float l = 0.f;
        #pragma unroll
        for (int t = 0; t < NTn; t++) l += lt[t] * __expf(mt[t] - m);
        m2[tid] = m; il2[tid] = 1.0f / l;
    }
    __syncthreads();
    const int q = tid & 127;
    const float mq = m2[q], ilq = il2[q];

    float acc[2][8][4];
    ZERO8(acc);
    const int m0 = (wid & 3) * 32, n0 = (wid >> 2) * 64;

    for (int tt = 0; tt < 2; tt++) {
        const int t = z * 2 + tt;
        if (tid < 128) cmadd[tid] = (1.0f - cmask[b * LCn + t * 128 + tid]) * NEGV;
        __syncthreads();

        {   // A = S2[q][c] hi
            const float* gS = g_S + (size_t)(b * LCn + t * 128) * LQn;
            #pragma unroll 2
            for (int it = 0; it < 32; it++) {
                const int c2 = ((it * 256 + tid) >> 7) * 2;
                float e0 = __expf(gS[c2 * LQn + q]       + cmadd[c2]     - mq) * ilq;
                float e1 = __expf(gS[(c2 + 1) * LQn + q] + cmadd[c2 + 1] - mq) * ilq;
                *(uint32_t*)(sb + A_HI + soff(q, c2)) = pack_hi(e0, e1);
            }
        }
        {   // B = C[d][c] hi/lo
            const float* Cg = C + (size_t)b * Dn * LCn + t * 128;
            const int c2 = (tid & 63) * 2;
            #pragma unroll 2
            for (int it = 0; it < 32; it++) {
                const int d = (it * 256 + tid) >> 6;
                float2 v = *(const float2*)(Cg + (size_t)d * LCn + c2);
                uint2 p = split_pair(v.x, v.y);
                uint32_t o = soff(d, c2);
                *(uint32_t*)(sb + B_HI + o) = p.x;
                *(uint32_t*)(sb + B_LO + o) = p.y;
            }
        }
        __syncthreads();
        gemm2(sb32, m0, n0, lane, acc);
        __syncthreads();
    }

    const int g = lane >> 2, l4 = lane & 3;
    #pragma unroll
    for (int mi = 0; mi < 2; mi++)
        #pragma unroll
        for (int ni = 0; ni < 8; ni++) {
            const int row = m0 + mi * 16 + g, col = n0 + ni * 8 + l4 * 2;
            *(float2*)&bounce[row * 132 + col] = make_float2(acc[mi][ni][0], acc[mi][ni][1]);
            *(float2*)&bounce[(row + 8) * 132 + col] = make_float2(acc[mi][ni][2], acc[mi][ni][3]);
        }
    __syncthreads();
    float* tp = g_Tp + (size_t)(b * 4 + z) * LQn * Dn;
    #pragma unroll 4
    for (int i = tid; i < 4096; i += 256) {
        int r = i >> 5, s = i & 31;
        *(float4*)(tp + r * Dn + s * 4) = *(float4*)(bounce + r * 132 + s * 4);
    }
}

// =====================================================================
// K4: S1 softmax; dual GEMM on a 128c x 64d half (blockIdx.z picks half);
//     T summed from partials inline; fused 4-section epilogue.
// =====================================================================
__global__ __launch_bounds__(256, 2) void k4_final(const float* __restrict__ C,
                                                   const float* __restrict__ Q,
                                                   const float* __restrict__ qmask,
                                                   float* __restrict__ out)
{
    extern __shared__ char sb[];
    const uint32_t sb32 = s2u(sb);
    float* qmadd = (float*)(sb + SMALL);
    float* m1    = (float*)(sb + SMALL + 512);
    float* il1   = (float*)(sb + SMALL + 1024);

    const int tid = threadIdx.x, wid = tid >> 5, lane = tid & 31;
    const int b = blockIdx.y, t = blockIdx.x, c0 = t * 128;
    const int dh0 = blockIdx.z * 64;

    if (tid < 128) qmadd[tid] = (1.0f - qmask[b * LQn + tid]) * NEGV;
    __syncthreads();

    const float* gS = g_S + (size_t)(b * LCn + c0) * LQn;

    for (int c = wid; c < 128; c += 8) {
        float x0 = gS[c * LQn + lane]      + qmadd[lane];
        float x1 = gS[c * LQn + lane + 32] + qmadd[lane + 32];
        float x2 = gS[c * LQn + lane + 64] + qmadd[lane + 64];
        float x3 = gS[c * LQn + lane + 96] + qmadd[lane + 96];
        float m = fmaxf(fmaxf(x0, x1), fmaxf(x2, x3));
        #pragma unroll
        for (int off = 16; off; off >>= 1) m = fmaxf(m, __shfl_xor_sync(~0u, m, off));
        float l = __expf(x0 - m) + __expf(x1 - m) + __expf(x2 - m) + __expf(x3 - m);
        #pragma unroll
        for (int off = 16; off; off >>= 1) l += __shfl_xor_sync(~0u, l, off);
        if (lane == 0) { m1[c] = m; il1[c] = 1.0f / l; }
    }
    __syncthreads();

    {   // A = S1[c][q] hi (full 128x128)
        const int q2 = (tid & 63) * 2;
        const float qa0 = qmadd[q2], qa1 = qmadd[q2 + 1];
        #pragma unroll 2
        for (int it = 0; it < 32; it++) {
            const int c = (it * 256 + tid) >> 6;
            float2 v = *(const float2*)(gS + c * LQn + q2);
            float m = m1[c], il = il1[c];
            *(uint32_t*)(sb + A_HI + soff(c, q2)) =
                pack_hi(__expf(v.x + qa0 - m) * il, __expf(v.y + qa1 - m) * il);
        }
    }
    {   // B1 = Q[dh0+d][q] hi/lo, 64 rows x 128 q
        const float* Qg = Q + (size_t)b * Dn * LQn + (size_t)dh0 * LQn;
        const int q2 = (tid & 63) * 2;
        #pragma unroll 2
        for (int it = 0; it < 16; it++) {
            const int d = (it * 256 + tid) >> 6;
            float2 v = *(const float2*)(Qg + d * LQn + q2);
            uint2 p = split_pair(v.x, v.y);
            uint32_t o = soff(d, q2);
            *(uint32_t*)(sb + B1H + o) = p.x;
            *(uint32_t*)(sb + B1L + o) = p.y;
        }
    }
    {   // B2[d][q] = sum_z Tp[z][q][dh0+d] hi/lo (transpose + reduce).
        // 64 d-rows: pair along d -> d2 = (i&31)*2 in 0..62, qq = i>>5 in 0..127.
        const float* tp = g_Tp + (size_t)b * 4 * LQn * Dn + dh0;
        #pragma unroll 2
        for (int it = 0; it < 16; it++) {
            const int i = it * 256 + tid;
            const int d2 = (i & 31) * 2;
            const int qq = i >> 5;
            float2 v0 = *(const float2*)(tp + qq * Dn + d2);
            float2 v1 = *(const float2*)(tp + 16384 + qq * Dn + d2);
            float2 v2 = *(const float2*)(tp + 32768 + qq * Dn + d2);
            float2 v3 = *(const float2*)(tp + 49152 + qq * Dn + d2);
            float sx = (v0.x + v1.x) + (v2.x + v3.x);
            float sy = (v0.y + v1.y) + (v2.y + v3.y);
            __half h0 = __float2half_rn(sx);
            __half l0 = __float2half_rn(sx - __half2float(h0));
            __half h1 = __float2half_rn(sy);
            __half l1 = __float2half_rn(sy - __half2float(h1));
            uint32_t o0 = soff(d2, qq), o1 = soff(d2 + 1, qq);
            *(__half*)(sb + B2H + o0) = h0;
            *(__half*)(sb + B2L + o0) = l0;
            *(__half*)(sb + B2H + o1) = h1;
            *(__half*)(sb + B2L + o1) = l1;
        }
    }
    __syncthreads();

    // Dual GEMM, warp tile 32c x 32d, shared A fragments
    float acc1[2][4][4], acc2[2][4][4];
    ZERO4(acc1); ZERO4(acc2);
    const int m0 = (wid & 3) * 32, n0 = (wid >> 2) * 32;
    {
        const int arow = lane & 15, achk = (lane >> 4) << 3;
        const int brow = ((lane >> 4) << 3) | (lane & 7);
        const int bchk = ((lane >> 3) & 1) << 3;
        #pragma unroll
        for (int ks = 0; ks < 8; ks++) {
            uint32_t ah[2][4];
            #pragma unroll
            for (int mi = 0; mi < 2; mi++)
                ld4(sb32 + A_HI + soff(m0 + mi * 16 + arow, ks * 16 + achk), ah[mi]);
            uint32_t b1h[8], b1l[8], b2h[8], b2l[8];
            #pragma unroll
            for (int p = 0; p < 2; p++) {
                uint32_t o = soff(n0 + p * 16 + brow, ks * 16 + bchk);
                ld4(sb32 + B1H + o, &b1h[p * 4]);
                ld4(sb32 + B1L + o, &b1l[p * 4]);
                ld4(sb32 + B2H + o, &b2h[p * 4]);
                ld4(sb32 + B2L + o, &b2l[p * 4]);
            }
            #pragma unroll
            for (int mi = 0; mi < 2; mi++)
                #pragma unroll
                for (int ni = 0; ni < 4; ni++) {
                    mma16(acc1[mi][ni], ah[mi], b1h[ni * 2], b1h[ni * 2 + 1]);
                    mma16(acc1[mi][ni], ah[mi], b1l[ni * 2], b1l[ni * 2 + 1]);
                    mma16(acc2[mi][ni], ah[mi], b2h[ni * 2], b2h[ni * 2 + 1]);
                    mma16(acc2[mi][ni], ah[mi], b2l[ni * 2], b2l[ni * 2 + 1]);
                }
        }
    }
    __syncthreads();   // operands dead; bounces overlay

    float* bnc1 = (float*)sb;                  // [d 64][c 132]
    float* bnc2 = (float*)(sb + 36864);
    const int g = lane >> 2, l4 = lane & 3;
    #pragma unroll
    for (int mi = 0; mi < 2; mi++)
        #pragma unroll
        for (int ni = 0; ni < 4; ni++) {
            const int row = m0 + mi * 16 + g, col = n0 + ni * 8 + l4 * 2;
            bnc1[col * 132 + row]           = acc1[mi][ni][0];
            bnc1[(col + 1) * 132 + row]     = acc1[mi][ni][1];
            bnc1[col * 132 + row + 8]       = acc1[mi][ni][2];
            bnc1[(col + 1) * 132 + row + 8] = acc1[mi][ni][3];
            bnc2[col * 132 + row]           = acc2[mi][ni][0];
            bnc2[(col + 1) * 132 + row]     = acc2[mi][ni][1];
            bnc2[col * 132 + row + 8]       = acc2[mi][ni][2];
            bnc2[(col + 1) * 132 + row + 8] = acc2[mi][ni][3];
        }
    __syncthreads();

    // Fused epilogue: this CTA's 64 d-rows of all 4 sections, one C read
    float* outB = out + (size_t)b * 4 * Dn * LCn;
    const float* Cb = C + (size_t)b * Dn * LCn;
    #pragma unroll 2
    for (int i = tid; i < 2048; i += 256) {
        int dl = i >> 5, c4 = (i & 31) * 4;
        int d = dh0 + dl;
        float4 a  = *(float4*)(bnc1 + dl * 132 + c4);
        float4 bt = *(float4*)(bnc2 + dl * 132 + c4);
        float4 cv = *(const float4*)(Cb + (size_t)d * LCn + c0 + c4);
        *(float4*)(outB + (size_t)d * LCn + c0 + c4) = cv;
        *(float4*)(outB + (size_t)(128 + d) * LCn + c0 + c4) = a;
        *(float4*)(outB + (size_t)(256 + d) * LCn + c0 + c4) =
            make_float4(cv.x * a.x, cv.y * a.y, cv.z * a.z, cv.w * a.w);
        *(float4*)(outB + (size_t)(384 + d) * LCn + c0 + c4) =
            make_float4(cv.x * bt.x, cv.y * bt.y, cv.z * bt.z, cv.w * bt.w);
    }
}

// ---------------------------------------------------------------------------
extern "C" void kernel_launch(void* const* d_in, const int* in_sizes, int n_in,
                              void* d_out, int out_size)
{
    const float* C     = (const float*)d_in[0];
    const float* Q     = (const float*)d_in[1];
    const float* cmask = (const float*)d_in[2];
    const float* qmask = (const float*)d_in[3];
    const float* w     = (const float*)d_in[4];
    float* out = (float*)d_out;

    cudaFuncSetAttribute(k1_S,     cudaFuncAttributeMaxDynamicSharedMemorySize, SMEM1);
    cudaFuncSetAttribute(k3_T,     cudaFuncAttributeMaxDynamicSharedMemorySize, SMEM3);
    cudaFuncSetAttribute(k4_final, cudaFuncAttributeMaxDynamicSharedMemorySize, SMEM4);

    k1_S<<<dim3(NTn, Bn), 256, SMEM1>>>(C, Q, cmask, w);
    k3_T<<<dim3(4, Bn), 256, SMEM3>>>(C, cmask);
    k4_final<<<dim3(NTn, Bn, 2), 256, SMEM4>>>(C, Q, qmask, out);
}